// round 1
// baseline (speedup 1.0000x reference)
#include <cuda_runtime.h>
#include <cuda_bf16.h>
#include <math.h>

// ---------------------------------------------------------------------------
// Problem constants (fixed by the reference)
// ---------------------------------------------------------------------------
#define D_MODEL   1024
#define D_STATE   16
#define D_CONV    4
#define D_INNER   2048      // 2 * D_MODEL
#define DT_RANK   64        // ceil(1024/16)
#define BATCH     2
#define SEQLEN    1024
#define ROWS      (BATCH * SEQLEN)          // 2048
#define XDBL_COLS (DT_RANK + 2 * D_STATE)   // 96
#define EPS       1e-5f

// ---------------------------------------------------------------------------
// Scratch (no cudaMalloc allowed -> __device__ globals)
// ---------------------------------------------------------------------------
__device__ float g_h   [ROWS * D_MODEL];      //  8 MB  rmsnorm output
__device__ float g_xz  [ROWS * 2 * D_INNER];  // 32 MB  in_proj output (x | z)
__device__ float g_xc  [ROWS * D_INNER];      // 16 MB  conv+silu output
__device__ float g_xdbl[ROWS * XDBL_COLS];    //  0.75MB x_proj output (dt_lowrank | B | C)
__device__ float g_dt  [ROWS * D_INNER];      // 16 MB  softplus(dt) (epilogue applied)
__device__ float g_y   [ROWS * D_INNER];      // 16 MB  scan output * silu(z)

// ---------------------------------------------------------------------------
// RMSNorm: one block per row of 1024
// ---------------------------------------------------------------------------
__global__ __launch_bounds__(256)
void rmsnorm_kernel(const float* __restrict__ x, const float* __restrict__ w,
                    float* __restrict__ out)
{
    int r = blockIdx.x;
    int t = threadIdx.x;
    const float4* xr = (const float4*)(x + (size_t)r * D_MODEL);
    float4 v = xr[t];
    float s = v.x * v.x + v.y * v.y + v.z * v.z + v.w * v.w;
    #pragma unroll
    for (int o = 16; o; o >>= 1) s += __shfl_xor_sync(0xffffffffu, s, o);

    __shared__ float ws[8];
    __shared__ float s_inv;
    if ((t & 31) == 0) ws[t >> 5] = s;
    __syncthreads();
    if (t == 0) {
        float tot = 0.f;
        #pragma unroll
        for (int i = 0; i < 8; i++) tot += ws[i];
        float rms = sqrtf(tot) * (1.0f / 32.0f);   // norm / sqrt(1024)
        s_inv = 1.0f / (rms + EPS);
    }
    __syncthreads();
    float inv = s_inv;
    float4 wv = ((const float4*)w)[t];
    float4 o;
    o.x = v.x * inv * wv.x;
    o.y = v.y * inv * wv.y;
    o.z = v.z * inv * wv.z;
    o.w = v.w * inv * wv.w;
    ((float4*)(out + (size_t)r * D_MODEL))[t] = o;
}

// ---------------------------------------------------------------------------
// Generic SGEMM:  C[m][n] = sum_k X[m][k] * W[n][k]   (+ optional softplus(.+bias[n]))
// X row-major (lda), W row-major (ldb), C row-major (ldc).
// Requires: M % BM == 0, K % BK == 0. N guarded.
// ---------------------------------------------------------------------------
__device__ __forceinline__ float softplusf(float v)
{
    return v > 20.f ? v : log1pf(__expf(v));
}

template<int BM, int BN, int BK, int TM, int TN, int EPI>
__global__ __launch_bounds__((BM / TM) * (BN / TN))
void gemm_xt_kernel(const float* __restrict__ X, int lda,
                    const float* __restrict__ W, int ldb,
                    float*       __restrict__ C, int ldc,
                    int M, int N, int K,
                    const float* __restrict__ bias)
{
    constexpr int THREADS = (BM / TM) * (BN / TN);
    constexpr int KV = BK / 4;                   // float4 slots along K
    constexpr int AITER = THREADS / KV;
    constexpr int BITER = THREADS / KV;

    __shared__ float As[BK][BM];
    __shared__ float Bs[BK][BN];

    int tid = threadIdx.x;
    int bm = blockIdx.y * BM;
    int bn = blockIdx.x * BN;

    int tcol = tid % (BN / TN);
    int trow = tid / (BN / TN);

    int lrow = tid / KV;         // row within tile for loading
    int lcol = tid % KV;         // float4 column within BK

    float acc[TM][TN] = {};

    for (int k0 = 0; k0 < K; k0 += BK) {
        // load X tile (BM x BK), transpose into As[k][m]
        #pragma unroll
        for (int r = 0; r < BM; r += AITER) {
            int row = r + lrow;
            float4 v = *(const float4*)(X + (size_t)(bm + row) * lda + k0 + lcol * 4);
            As[lcol * 4 + 0][row] = v.x;
            As[lcol * 4 + 1][row] = v.y;
            As[lcol * 4 + 2][row] = v.z;
            As[lcol * 4 + 3][row] = v.w;
        }
        // load W tile (BN x BK), transpose into Bs[k][n]
        #pragma unroll
        for (int r = 0; r < BN; r += BITER) {
            int row = r + lrow;
            int gn = bn + row;
            float4 v = make_float4(0.f, 0.f, 0.f, 0.f);
            if (gn < N)
                v = *(const float4*)(W + (size_t)gn * ldb + k0 + lcol * 4);
            Bs[lcol * 4 + 0][row] = v.x;
            Bs[lcol * 4 + 1][row] = v.y;
            Bs[lcol * 4 + 2][row] = v.z;
            Bs[lcol * 4 + 3][row] = v.w;
        }
        __syncthreads();

        #pragma unroll
        for (int k = 0; k < BK; k++) {
            float a[TM], b[TN];
            #pragma unroll
            for (int i = 0; i < TM; i++) a[i] = As[k][trow * TM + i];
            #pragma unroll
            for (int j = 0; j < TN; j++) b[j] = Bs[k][tcol * TN + j];
            #pragma unroll
            for (int i = 0; i < TM; i++)
                #pragma unroll
                for (int j = 0; j < TN; j++)
                    acc[i][j] = fmaf(a[i], b[j], acc[i][j]);
        }
        __syncthreads();
    }

    #pragma unroll
    for (int i = 0; i < TM; i++) {
        int gm = bm + trow * TM + i;
        #pragma unroll
        for (int j = 0; j < TN; j++) {
            int gn = bn + tcol * TN + j;
            if (gn < N) {
                float v = acc[i][j];
                if (EPI == 1) v = softplusf(v + bias[gn]);
                C[(size_t)gm * ldc + gn] = v;
            }
        }
    }
}

// ---------------------------------------------------------------------------
// Depthwise causal conv (kernel 4) + bias + SiLU.
// Reads x = g_xz[:, 0:D_INNER]; writes g_xc.
// ---------------------------------------------------------------------------
__global__ __launch_bounds__(256)
void conv_silu_kernel(const float* __restrict__ xz,
                      const float* __restrict__ cw,
                      const float* __restrict__ cb,
                      float* __restrict__ xc)
{
    int idx = blockIdx.x * blockDim.x + threadIdx.x;   // over ROWS * D_INNER
    if (idx >= ROWS * D_INNER) return;
    int d = idx & (D_INNER - 1);
    int r = idx >> 11;           // / D_INNER
    int l = r & (SEQLEN - 1);
    int b = r >> 10;

    float acc = cb[d];
    #pragma unroll
    for (int k = 0; k < D_CONV; k++) {
        int ls = l + k - (D_CONV - 1);
        if (ls >= 0)
            acc = fmaf(xz[((size_t)(b * SEQLEN + ls)) * (2 * D_INNER) + d],
                       cw[d * D_CONV + k], acc);
    }
    float sig = 1.0f / (1.0f + __expf(-acc));
    xc[idx] = acc * sig;
}

// ---------------------------------------------------------------------------
// Selective scan. 16 lanes per (b,d) channel, one state per lane.
// dt already has softplus applied (GEMM epilogue).
// Writes y = (scan + D*xc) * silu(z).
// ---------------------------------------------------------------------------
__global__ __launch_bounds__(128)
void scan_kernel(const float* __restrict__ xdbl,
                 const float* __restrict__ dt,
                 const float* __restrict__ xc,
                 const float* __restrict__ xz,
                 const float* __restrict__ A_log,
                 const float* __restrict__ Dw,
                 float* __restrict__ y)
{
    int t = blockIdx.x * blockDim.x + threadIdx.x;   // 0 .. 65535
    int n  = t & (D_STATE - 1);
    int ch = t >> 4;                                  // 0 .. 4095
    int b  = ch >> 11;                                // / D_INNER
    int d  = ch & (D_INNER - 1);

    float A  = -__expf(A_log[d * D_STATE + n]);
    float Dd = Dw[d];

    const float* xdbl_b = xdbl + (size_t)b * SEQLEN * XDBL_COLS;
    const float* dt_b   = dt   + (size_t)b * SEQLEN * D_INNER + d;
    const float* xc_b   = xc   + (size_t)b * SEQLEN * D_INNER + d;
    const float* z_b    = xz   + (size_t)b * SEQLEN * (2 * D_INNER) + D_INNER + d;
    float*       y_b    = y    + (size_t)b * SEQLEN * D_INNER + d;

    float h = 0.f;
    for (int l = 0; l < SEQLEN; l++) {
        float dtv = dt_b[(size_t)l * D_INNER];
        float xcv = xc_b[(size_t)l * D_INNER];
        float Bv  = xdbl_b[l * XDBL_COLS + DT_RANK + n];
        float Cv  = xdbl_b[l * XDBL_COLS + DT_RANK + D_STATE + n];

        float dA = __expf(dtv * A);
        h = fmaf(dA, h, dtv * xcv * Bv);

        float p = h * Cv;
        p += __shfl_xor_sync(0xffffffffu, p, 8);
        p += __shfl_xor_sync(0xffffffffu, p, 4);
        p += __shfl_xor_sync(0xffffffffu, p, 2);
        p += __shfl_xor_sync(0xffffffffu, p, 1);

        if (n == 0) {
            float zv  = z_b[(size_t)l * (2 * D_INNER)];
            float sil = zv / (1.0f + __expf(-zv));
            y_b[(size_t)l * D_INNER] = (p + Dd * xcv) * sil;
        }
    }
}

// ---------------------------------------------------------------------------
// Launch
// ---------------------------------------------------------------------------
extern "C" void kernel_launch(void* const* d_in, const int* in_sizes, int n_in,
                              void* d_out, int out_size)
{
    const float* hidden   = (const float*)d_in[0];
    const float* norm_w   = (const float*)d_in[1];
    const float* in_proj  = (const float*)d_in[2];
    const float* conv_w   = (const float*)d_in[3];
    const float* conv_b   = (const float*)d_in[4];
    const float* x_proj   = (const float*)d_in[5];
    const float* dt_proj  = (const float*)d_in[6];
    const float* dt_b     = (const float*)d_in[7];
    const float* A_log    = (const float*)d_in[8];
    const float* Dw       = (const float*)d_in[9];
    const float* out_proj = (const float*)d_in[10];

    float* out = (float*)d_out;

    float *h, *xz, *xc, *xdbl, *dt, *y;
    cudaGetSymbolAddress((void**)&h,    g_h);
    cudaGetSymbolAddress((void**)&xz,   g_xz);
    cudaGetSymbolAddress((void**)&xc,   g_xc);
    cudaGetSymbolAddress((void**)&xdbl, g_xdbl);
    cudaGetSymbolAddress((void**)&dt,   g_dt);
    cudaGetSymbolAddress((void**)&y,    g_y);

    // 1. RMSNorm
    rmsnorm_kernel<<<ROWS, 256>>>(hidden, norm_w, h);

    // 2. in_proj: (2048 x 1024) @ (4096 x 1024)^T -> (2048 x 4096)
    {
        dim3 grid(2 * D_INNER / 128, ROWS / 128);
        gemm_xt_kernel<128,128,16,8,8,0><<<grid, 256>>>(
            h, D_MODEL, in_proj, D_MODEL, xz, 2 * D_INNER,
            ROWS, 2 * D_INNER, D_MODEL, nullptr);
    }

    // 3. conv + silu
    conv_silu_kernel<<<(ROWS * D_INNER) / 256, 256>>>(xz, conv_w, conv_b, xc);

    // 4. x_proj: (2048 x 2048) @ (96 x 2048)^T -> (2048 x 96)
    {
        dim3 grid((XDBL_COLS + 31) / 32, ROWS / 64);
        gemm_xt_kernel<64,32,64,4,2,0><<<grid, 256>>>(
            xc, D_INNER, x_proj, D_INNER, xdbl, XDBL_COLS,
            ROWS, XDBL_COLS, D_INNER, nullptr);
    }

    // 5. dt_proj + softplus epilogue: (2048 x 64) @ (2048 x 64)^T -> (2048 x 2048)
    {
        dim3 grid(D_INNER / 128, ROWS / 128);
        gemm_xt_kernel<128,128,16,8,8,1><<<grid, 256>>>(
            xdbl, XDBL_COLS, dt_proj, DT_RANK, dt, D_INNER,
            ROWS, D_INNER, DT_RANK, dt_b);
    }

    // 6. selective scan + gate
    scan_kernel<<<(BATCH * D_INNER * D_STATE) / 128, 128>>>(
        xdbl, dt, xc, xz, A_log, Dw, y);

    // 7. out_proj: (2048 x 2048) @ (1024 x 2048)^T -> (2048 x 1024)
    {
        dim3 grid(D_MODEL / 128, ROWS / 128);
        gemm_xt_kernel<128,128,16,8,8,0><<<grid, 256>>>(
            y, D_INNER, out_proj, D_INNER, out, D_MODEL,
            ROWS, D_MODEL, D_INNER, nullptr);
    }

    // 8. residual = hidden_states (second half of output)
    size_t half = (size_t)out_size / 2;
    cudaMemcpyAsync(out + half, hidden, half * sizeof(float),
                    cudaMemcpyDeviceToDevice);
}

// round 2
// speedup vs baseline: 1.4156x; 1.4156x over previous
#include <cuda_runtime.h>
#include <cuda_bf16.h>
#include <math.h>

// ---------------------------------------------------------------------------
// Problem constants (fixed by the reference)
// ---------------------------------------------------------------------------
#define D_MODEL   1024
#define D_STATE   16
#define D_CONV    4
#define D_INNER   2048      // 2 * D_MODEL
#define DT_RANK   64        // ceil(1024/16)
#define BATCH     2
#define SEQLEN    1024
#define ROWS      (BATCH * SEQLEN)          // 2048
#define XDBL_COLS (DT_RANK + 2 * D_STATE)   // 96
#define EPS       1e-5f

// ---------------------------------------------------------------------------
// Scratch (no cudaMalloc allowed -> __device__ globals)
// ---------------------------------------------------------------------------
__device__ float g_h   [ROWS * D_MODEL];      // rmsnorm output
__device__ float g_xz  [ROWS * 2 * D_INNER];  // in_proj output (x | z)
__device__ float g_xc  [ROWS * D_INNER];      // conv+silu output
__device__ float g_xdbl[ROWS * XDBL_COLS];    // x_proj output (dt_lowrank | B | C)
__device__ float g_dt  [ROWS * D_INNER];      // softplus(dt) (epilogue applied)
__device__ float g_y   [ROWS * D_INNER];      // scan output * silu(z)

// ---------------------------------------------------------------------------
// RMSNorm: one block per row of 1024
// ---------------------------------------------------------------------------
__global__ __launch_bounds__(256)
void rmsnorm_kernel(const float* __restrict__ x, const float* __restrict__ w,
                    float* __restrict__ out)
{
    int r = blockIdx.x;
    int t = threadIdx.x;
    const float4* xr = (const float4*)(x + (size_t)r * D_MODEL);
    float4 v = xr[t];
    float s = v.x * v.x + v.y * v.y + v.z * v.z + v.w * v.w;
    #pragma unroll
    for (int o = 16; o; o >>= 1) s += __shfl_xor_sync(0xffffffffu, s, o);

    __shared__ float ws[8];
    __shared__ float s_inv;
    if ((t & 31) == 0) ws[t >> 5] = s;
    __syncthreads();
    if (t == 0) {
        float tot = 0.f;
        #pragma unroll
        for (int i = 0; i < 8; i++) tot += ws[i];
        float rms = sqrtf(tot) * (1.0f / 32.0f);   // norm / sqrt(1024)
        s_inv = 1.0f / (rms + EPS);
    }
    __syncthreads();
    float inv = s_inv;
    float4 wv = ((const float4*)w)[t];
    float4 o;
    o.x = v.x * inv * wv.x;
    o.y = v.y * inv * wv.y;
    o.z = v.z * inv * wv.z;
    o.w = v.w * inv * wv.w;
    ((float4*)(out + (size_t)r * D_MODEL))[t] = o;
}

// ---------------------------------------------------------------------------
// TF32 tensor-core GEMM:  C[m][n] = sum_k X[m][k] * W[n][k]
//   (+ optional softplus(. + bias[n]) epilogue)
// Block tile 128x64, BK=16, 8 warps, warp tile 32x32, mma.sync m16n8k8.tf32.
// Requires M % 128 == 0, K % 16 == 0. N guarded.
// ---------------------------------------------------------------------------
__device__ __forceinline__ unsigned f2tf(float f)
{
    unsigned r;
    asm("cvt.rna.tf32.f32 %0, %1;" : "=r"(r) : "f"(f));
    return r;
}

__device__ __forceinline__ void mma_tf32(float c[4],
                                         unsigned a0, unsigned a1,
                                         unsigned a2, unsigned a3,
                                         unsigned b0, unsigned b1)
{
    asm volatile(
        "mma.sync.aligned.m16n8k8.row.col.f32.tf32.tf32.f32 "
        "{%0,%1,%2,%3}, {%4,%5,%6,%7}, {%8,%9}, {%0,%1,%2,%3};"
        : "+f"(c[0]), "+f"(c[1]), "+f"(c[2]), "+f"(c[3])
        : "r"(a0), "r"(a1), "r"(a2), "r"(a3), "r"(b0), "r"(b1));
}

__device__ __forceinline__ float softplusf(float v)
{
    return v > 20.f ? v : log1pf(__expf(v));
}

#define TB_M 128
#define TB_N 64
#define TB_K 16
#define SK   20    // padded smem stride (conflict-free frag loads: bank=(4m+k)%32)

template<int EPI>
__global__ __launch_bounds__(256)
void gemm_tf32_kernel(const float* __restrict__ X, int lda,
                      const float* __restrict__ W, int ldb,
                      float*       __restrict__ C, int ldc,
                      int N, int K,
                      const float* __restrict__ bias)
{
    __shared__ unsigned As[2][TB_M][SK];
    __shared__ unsigned Bs[2][TB_N][SK];

    const int tid  = threadIdx.x;
    const int wid  = tid >> 5;
    const int lane = tid & 31;
    const int g    = lane >> 2;     // group id   (0..7)
    const int t    = lane & 3;      // thread-in-group (0..3)
    const int warpM = (wid & 3) * 32;   // 4 warps along M
    const int warpN = (wid >> 2) * 32;  // 2 warps along N

    const int bm = blockIdx.y * TB_M;
    const int bn = blockIdx.x * TB_N;

    // global-load mapping: A: 4 float4 per row of 16, 128 rows -> 2 passes
    const int la_row = tid >> 2;        // 0..63
    const int la_c4  = tid & 3;         // float4 index in BK
    const int lb_row = tid >> 2;        // 0..63 (B: 64 rows, 1 pass)
    const int lb_c4  = tid & 3;

    float acc[2][4][4];
    #pragma unroll
    for (int i = 0; i < 2; i++)
        #pragma unroll
        for (int j = 0; j < 4; j++)
            #pragma unroll
            for (int q = 0; q < 4; q++) acc[i][j][q] = 0.f;

    const int ktiles = K / TB_K;

    // ---- preload tile 0 into smem[0]
    {
        #pragma unroll
        for (int p = 0; p < 2; p++) {
            int row = la_row + p * 64;
            float4 v = *(const float4*)(X + (size_t)(bm + row) * lda + la_c4 * 4);
            As[0][row][la_c4 * 4 + 0] = f2tf(v.x);
            As[0][row][la_c4 * 4 + 1] = f2tf(v.y);
            As[0][row][la_c4 * 4 + 2] = f2tf(v.z);
            As[0][row][la_c4 * 4 + 3] = f2tf(v.w);
        }
        int gn = bn + lb_row;
        float4 v = make_float4(0.f, 0.f, 0.f, 0.f);
        if (gn < N)
            v = *(const float4*)(W + (size_t)gn * ldb + lb_c4 * 4);
        Bs[0][lb_row][lb_c4 * 4 + 0] = f2tf(v.x);
        Bs[0][lb_row][lb_c4 * 4 + 1] = f2tf(v.y);
        Bs[0][lb_row][lb_c4 * 4 + 2] = f2tf(v.z);
        Bs[0][lb_row][lb_c4 * 4 + 3] = f2tf(v.w);
    }
    __syncthreads();

    for (int kt = 0; kt < ktiles; kt++) {
        const int cur = kt & 1;
        const int nxt = cur ^ 1;
        float4 pa0, pa1, pb;
        const bool has_next = (kt + 1 < ktiles);
        if (has_next) {
            int k0 = (kt + 1) * TB_K;
            pa0 = *(const float4*)(X + (size_t)(bm + la_row) * lda + k0 + la_c4 * 4);
            pa1 = *(const float4*)(X + (size_t)(bm + la_row + 64) * lda + k0 + la_c4 * 4);
            int gn = bn + lb_row;
            pb = make_float4(0.f, 0.f, 0.f, 0.f);
            if (gn < N)
                pb = *(const float4*)(W + (size_t)gn * ldb + k0 + lb_c4 * 4);
        }

        // ---- compute on smem[cur]
        #pragma unroll
        for (int kk = 0; kk < 2; kk++) {
            const int k = kk * 8 + t;
            unsigned a[2][4];
            #pragma unroll
            for (int mt = 0; mt < 2; mt++) {
                int m = warpM + mt * 16 + g;
                a[mt][0] = As[cur][m    ][k    ];
                a[mt][1] = As[cur][m + 8][k    ];
                a[mt][2] = As[cur][m    ][k + 4];
                a[mt][3] = As[cur][m + 8][k + 4];
            }
            #pragma unroll
            for (int nt = 0; nt < 4; nt++) {
                int n = warpN + nt * 8 + g;
                unsigned b0 = Bs[cur][n][k];
                unsigned b1 = Bs[cur][n][k + 4];
                #pragma unroll
                for (int mt = 0; mt < 2; mt++)
                    mma_tf32(acc[mt][nt], a[mt][0], a[mt][1], a[mt][2], a[mt][3], b0, b1);
            }
        }

        if (has_next) {
            As[nxt][la_row     ][la_c4 * 4 + 0] = f2tf(pa0.x);
            As[nxt][la_row     ][la_c4 * 4 + 1] = f2tf(pa0.y);
            As[nxt][la_row     ][la_c4 * 4 + 2] = f2tf(pa0.z);
            As[nxt][la_row     ][la_c4 * 4 + 3] = f2tf(pa0.w);
            As[nxt][la_row + 64][la_c4 * 4 + 0] = f2tf(pa1.x);
            As[nxt][la_row + 64][la_c4 * 4 + 1] = f2tf(pa1.y);
            As[nxt][la_row + 64][la_c4 * 4 + 2] = f2tf(pa1.z);
            As[nxt][la_row + 64][la_c4 * 4 + 3] = f2tf(pa1.w);
            Bs[nxt][lb_row][lb_c4 * 4 + 0] = f2tf(pb.x);
            Bs[nxt][lb_row][lb_c4 * 4 + 1] = f2tf(pb.y);
            Bs[nxt][lb_row][lb_c4 * 4 + 2] = f2tf(pb.z);
            Bs[nxt][lb_row][lb_c4 * 4 + 3] = f2tf(pb.w);
        }
        __syncthreads();
    }

    // ---- epilogue
    #pragma unroll
    for (int mt = 0; mt < 2; mt++) {
        #pragma unroll
        for (int nt = 0; nt < 4; nt++) {
            int gm0 = bm + warpM + mt * 16 + g;
            int gn0 = bn + warpN + nt * 8 + t * 2;
            if (gn0 < N) {
                float2 v0 = make_float2(acc[mt][nt][0], acc[mt][nt][1]);
                float2 v1 = make_float2(acc[mt][nt][2], acc[mt][nt][3]);
                if (EPI == 1) {
                    float b0 = bias[gn0], b1 = bias[gn0 + 1];
                    v0.x = softplusf(v0.x + b0);
                    v0.y = softplusf(v0.y + b1);
                    v1.x = softplusf(v1.x + b0);
                    v1.y = softplusf(v1.y + b1);
                }
                *(float2*)(C + (size_t)gm0 * ldc + gn0)       = v0;
                *(float2*)(C + (size_t)(gm0 + 8) * ldc + gn0) = v1;
            }
        }
    }
}

// ---------------------------------------------------------------------------
// Depthwise causal conv (kernel 4) + bias + SiLU.
// ---------------------------------------------------------------------------
__global__ __launch_bounds__(256)
void conv_silu_kernel(const float* __restrict__ xz,
                      const float* __restrict__ cw,
                      const float* __restrict__ cb,
                      float* __restrict__ xc)
{
    int idx = blockIdx.x * blockDim.x + threadIdx.x;   // over ROWS * D_INNER
    if (idx >= ROWS * D_INNER) return;
    int d = idx & (D_INNER - 1);
    int r = idx >> 11;           // / D_INNER
    int l = r & (SEQLEN - 1);
    int b = r >> 10;

    float acc = cb[d];
    #pragma unroll
    for (int k = 0; k < D_CONV; k++) {
        int ls = l + k - (D_CONV - 1);
        if (ls >= 0)
            acc = fmaf(xz[((size_t)(b * SEQLEN + ls)) * (2 * D_INNER) + d],
                       cw[d * D_CONV + k], acc);
    }
    float sig = 1.0f / (1.0f + __expf(-acc));
    xc[idx] = acc * sig;
}

// ---------------------------------------------------------------------------
// Selective scan. 16 lanes per (b,d) channel, one state per lane.
// ---------------------------------------------------------------------------
__global__ __launch_bounds__(128)
void scan_kernel(const float* __restrict__ xdbl,
                 const float* __restrict__ dt,
                 const float* __restrict__ xc,
                 const float* __restrict__ xz,
                 const float* __restrict__ A_log,
                 const float* __restrict__ Dw,
                 float* __restrict__ y)
{
    int t = blockIdx.x * blockDim.x + threadIdx.x;   // 0 .. 65535
    int n  = t & (D_STATE - 1);
    int ch = t >> 4;                                  // 0 .. 4095
    int b  = ch >> 11;                                // / D_INNER
    int d  = ch & (D_INNER - 1);

    float A  = -__expf(A_log[d * D_STATE + n]);
    float Dd = Dw[d];

    const float* xdbl_b = xdbl + (size_t)b * SEQLEN * XDBL_COLS;
    const float* dt_b   = dt   + (size_t)b * SEQLEN * D_INNER + d;
    const float* xc_b   = xc   + (size_t)b * SEQLEN * D_INNER + d;
    const float* z_b    = xz   + (size_t)b * SEQLEN * (2 * D_INNER) + D_INNER + d;
    float*       y_b    = y    + (size_t)b * SEQLEN * D_INNER + d;

    float h = 0.f;
    for (int l = 0; l < SEQLEN; l++) {
        float dtv = dt_b[(size_t)l * D_INNER];
        float xcv = xc_b[(size_t)l * D_INNER];
        float Bv  = xdbl_b[l * XDBL_COLS + DT_RANK + n];
        float Cv  = xdbl_b[l * XDBL_COLS + DT_RANK + D_STATE + n];

        float dA = __expf(dtv * A);
        h = fmaf(dA, h, dtv * xcv * Bv);

        float p = h * Cv;
        p += __shfl_xor_sync(0xffffffffu, p, 8);
        p += __shfl_xor_sync(0xffffffffu, p, 4);
        p += __shfl_xor_sync(0xffffffffu, p, 2);
        p += __shfl_xor_sync(0xffffffffu, p, 1);

        if (n == 0) {
            float zv  = z_b[(size_t)l * (2 * D_INNER)];
            float sil = zv / (1.0f + __expf(-zv));
            y_b[(size_t)l * D_INNER] = (p + Dd * xcv) * sil;
        }
    }
}

// ---------------------------------------------------------------------------
// Launch
// ---------------------------------------------------------------------------
extern "C" void kernel_launch(void* const* d_in, const int* in_sizes, int n_in,
                              void* d_out, int out_size)
{
    const float* hidden   = (const float*)d_in[0];
    const float* norm_w   = (const float*)d_in[1];
    const float* in_proj  = (const float*)d_in[2];
    const float* conv_w   = (const float*)d_in[3];
    const float* conv_b   = (const float*)d_in[4];
    const float* x_proj   = (const float*)d_in[5];
    const float* dt_proj  = (const float*)d_in[6];
    const float* dt_b     = (const float*)d_in[7];
    const float* A_log    = (const float*)d_in[8];
    const float* Dw       = (const float*)d_in[9];
    const float* out_proj = (const float*)d_in[10];

    float* out = (float*)d_out;

    float *h, *xz, *xc, *xdbl, *dt, *y;
    cudaGetSymbolAddress((void**)&h,    g_h);
    cudaGetSymbolAddress((void**)&xz,   g_xz);
    cudaGetSymbolAddress((void**)&xc,   g_xc);
    cudaGetSymbolAddress((void**)&xdbl, g_xdbl);
    cudaGetSymbolAddress((void**)&dt,   g_dt);
    cudaGetSymbolAddress((void**)&y,    g_y);

    // 1. RMSNorm
    rmsnorm_kernel<<<ROWS, 256>>>(hidden, norm_w, h);

    // 2. in_proj: (2048 x 1024) @ (4096 x 1024)^T -> (2048 x 4096)
    {
        dim3 grid(2 * D_INNER / TB_N, ROWS / TB_M);
        gemm_tf32_kernel<0><<<grid, 256>>>(
            h, D_MODEL, in_proj, D_MODEL, xz, 2 * D_INNER,
            2 * D_INNER, D_MODEL, nullptr);
    }

    // 3. conv + silu
    conv_silu_kernel<<<(ROWS * D_INNER) / 256, 256>>>(xz, conv_w, conv_b, xc);

    // 4. x_proj: (2048 x 2048) @ (96 x 2048)^T -> (2048 x 96)
    {
        dim3 grid((XDBL_COLS + TB_N - 1) / TB_N, ROWS / TB_M);
        gemm_tf32_kernel<0><<<grid, 256>>>(
            xc, D_INNER, x_proj, D_INNER, xdbl, XDBL_COLS,
            XDBL_COLS, D_INNER, nullptr);
    }

    // 5. dt_proj + softplus epilogue: (2048 x 96[:64]) @ (2048 x 64)^T -> (2048 x 2048)
    {
        dim3 grid(D_INNER / TB_N, ROWS / TB_M);
        gemm_tf32_kernel<1><<<grid, 256>>>(
            xdbl, XDBL_COLS, dt_proj, DT_RANK, dt, D_INNER,
            D_INNER, DT_RANK, dt_b);
    }

    // 6. selective scan + gate
    scan_kernel<<<(BATCH * D_INNER * D_STATE) / 128, 128>>>(
        xdbl, dt, xc, xz, A_log, Dw, y);

    // 7. out_proj: (2048 x 2048) @ (1024 x 2048)^T -> (2048 x 1024)
    {
        dim3 grid(D_MODEL / TB_N, ROWS / TB_M);
        gemm_tf32_kernel<0><<<grid, 256>>>(
            y, D_INNER, out_proj, D_INNER, out, D_MODEL,
            D_MODEL, D_INNER, nullptr);
    }

    // 8. residual = hidden_states (second half of output)
    size_t half = (size_t)out_size / 2;
    cudaMemcpyAsync(out + half, hidden, half * sizeof(float),
                    cudaMemcpyDeviceToDevice);
}

// round 3
// speedup vs baseline: 1.4386x; 1.0162x over previous
#include <cuda_runtime.h>
#include <cuda_bf16.h>
#include <math.h>

// ---------------------------------------------------------------------------
// Problem constants
// ---------------------------------------------------------------------------
#define D_MODEL   1024
#define D_STATE   16
#define D_CONV    4
#define D_INNER   2048
#define DT_RANK   64
#define BATCH     2
#define SEQLEN    1024
#define ROWS      (BATCH * SEQLEN)          // 2048
#define XDBL_COLS (DT_RANK + 2 * D_STATE)   // 96
#define EPS       1e-5f

#define XP_SPLITS 8
#define XP_KSPL   (D_INNER / XP_SPLITS)     // 256

// ---------------------------------------------------------------------------
// Scratch (__device__ globals; no cudaMalloc allowed)
// ---------------------------------------------------------------------------
__device__ unsigned g_ht  [ROWS * D_MODEL];            // rmsnorm out (tf32)
__device__ float    g_xz  [ROWS * 2 * D_INNER];        // in_proj out (x | z) fp32
__device__ float    g_xc  [ROWS * D_INNER];            // conv+silu fp32 (scan)
__device__ unsigned g_xct [ROWS * D_INNER];            // conv+silu tf32 (x_proj A)
__device__ float    g_xpart[XP_SPLITS * ROWS * XDBL_COLS]; // split-K partials
__device__ float    g_xdbl [ROWS * XDBL_COLS];         // x_proj out fp32 (scan B,C)
__device__ unsigned g_xdblt[ROWS * XDBL_COLS];         // x_proj out tf32 (dt A)
__device__ float    g_dt  [ROWS * D_INNER];            // softplus(dt) fp32
__device__ unsigned g_yt  [ROWS * D_INNER];            // scan out (tf32, out_proj A)
__device__ unsigned g_wi  [2 * D_INNER * D_MODEL];     // tf32 weights
__device__ unsigned g_wo  [D_MODEL * D_INNER];
__device__ unsigned g_wx  [XDBL_COLS * D_INNER];
__device__ unsigned g_wd  [D_INNER * DT_RANK];

// ---------------------------------------------------------------------------
// Helpers
// ---------------------------------------------------------------------------
__device__ __forceinline__ unsigned f2tf(float f)
{
    unsigned r;
    asm("cvt.rna.tf32.f32 %0, %1;" : "=r"(r) : "f"(f));
    return r;
}

__device__ __forceinline__ void mma_tf32(float c[4],
                                         unsigned a0, unsigned a1,
                                         unsigned a2, unsigned a3,
                                         unsigned b0, unsigned b1)
{
    asm volatile(
        "mma.sync.aligned.m16n8k8.row.col.f32.tf32.tf32.f32 "
        "{%0,%1,%2,%3}, {%4,%5,%6,%7}, {%8,%9}, {%0,%1,%2,%3};"
        : "+f"(c[0]), "+f"(c[1]), "+f"(c[2]), "+f"(c[3])
        : "r"(a0), "r"(a1), "r"(a2), "r"(a3), "r"(b0), "r"(b1));
}

__device__ __forceinline__ float softplusf(float v)
{
    return v > 20.f ? v : log1pf(__expf(v));
}

// ---------------------------------------------------------------------------
// Weight pre-conversion (fp32 -> tf32), all four weight matrices in one kernel
// ---------------------------------------------------------------------------
#define NWI (2 * D_INNER * D_MODEL)   // 4194304
#define NWO (D_MODEL * D_INNER)       // 2097152
#define NWX (XDBL_COLS * D_INNER)     // 196608
#define NWD (D_INNER * DT_RANK)       // 131072
#define NW_TOTAL (NWI + NWO + NWX + NWD)

__global__ __launch_bounds__(256)
void cvt_weights_kernel(const float* __restrict__ wi, const float* __restrict__ wo,
                        const float* __restrict__ wx, const float* __restrict__ wd)
{
    int i = blockIdx.x * 256 + threadIdx.x;
    if (i < NWI)                       g_wi[i] = f2tf(wi[i]);
    else if (i < NWI + NWO)            g_wo[i - NWI] = f2tf(wo[i - NWI]);
    else if (i < NWI + NWO + NWX)      g_wx[i - NWI - NWO] = f2tf(wx[i - NWI - NWO]);
    else if (i < NW_TOTAL)             g_wd[i - NWI - NWO - NWX] = f2tf(wd[i - NWI - NWO - NWX]);
}

// ---------------------------------------------------------------------------
// RMSNorm -> tf32
// ---------------------------------------------------------------------------
__global__ __launch_bounds__(256)
void rmsnorm_kernel(const float* __restrict__ x, const float* __restrict__ w,
                    unsigned* __restrict__ out)
{
    int r = blockIdx.x;
    int t = threadIdx.x;
    const float4* xr = (const float4*)(x + (size_t)r * D_MODEL);
    float4 v = xr[t];
    float s = v.x * v.x + v.y * v.y + v.z * v.z + v.w * v.w;
    #pragma unroll
    for (int o = 16; o; o >>= 1) s += __shfl_xor_sync(0xffffffffu, s, o);

    __shared__ float ws[8];
    __shared__ float s_inv;
    if ((t & 31) == 0) ws[t >> 5] = s;
    __syncthreads();
    if (t == 0) {
        float tot = 0.f;
        #pragma unroll
        for (int i = 0; i < 8; i++) tot += ws[i];
        float rms = sqrtf(tot) * (1.0f / 32.0f);
        s_inv = 1.0f / (rms + EPS);
    }
    __syncthreads();
    float inv = s_inv;
    float4 wv = ((const float4*)w)[t];
    uint4 o;
    o.x = f2tf(v.x * inv * wv.x);
    o.y = f2tf(v.y * inv * wv.y);
    o.z = f2tf(v.z * inv * wv.z);
    o.w = f2tf(v.w * inv * wv.w);
    ((uint4*)(out + (size_t)r * D_MODEL))[t] = o;
}

// ---------------------------------------------------------------------------
// TF32 tensor GEMM, cp.async 3-stage, 128x128x32 block tile, 8 warps (64x32 each)
//   C[m][n] = sum_k A[m][k] * B[n][k]    A,B pre-converted tf32 (as unsigned)
//   EPI==1: C = softplus(acc + bias[n])
//   split-K via blockIdx.z: k range [z*k_split, (z+1)*k_split), C += z*split_cstride
// Requires M % 128 == 0, k_split % 32 == 0. N guarded.
// ---------------------------------------------------------------------------
#define BK   32
#define STG  3
#define SKA  36                        // padded stride (bank = 4g+t, conflict-free)
#define TILE_WORDS  (128 * SKA)        // 4608
#define STAGE_WORDS (2 * TILE_WORDS)   // 9216
#define GEMM_SMEM   (STG * STAGE_WORDS * 4)  // 110592 B

template<int EPI>
__global__ __launch_bounds__(256, 2)
void gemm_tc(const unsigned* __restrict__ A, int lda,
             const unsigned* __restrict__ B, int ldb,
             float* __restrict__ C, int ldc,
             int N, int k_split, long long split_cstride,
             const float* __restrict__ bias)
{
    extern __shared__ unsigned sm[];
    const int tid = threadIdx.x;
    const int bm  = blockIdx.y * 128;
    const int bn  = blockIdx.x * 128;
    const int k0base = blockIdx.z * k_split;
    C += (size_t)blockIdx.z * split_cstride;
    const int ktiles = k_split / BK;

    const int wid  = tid >> 5, lane = tid & 31;
    const int g    = lane >> 2, t = lane & 3;
    const int warpM = (wid & 1) * 64;
    const int warpN = (wid >> 1) * 32;

    const int lrow = tid >> 3;     // 0..31 (x8 chunks per row handled below)
    const int lc8  = tid & 7;

    auto load_stage = [&](int stage, int kt) {
        const int k0 = k0base + kt * BK;
        unsigned sbase = (unsigned)__cvta_generic_to_shared(sm + stage * STAGE_WORDS);
        #pragma unroll
        for (int i = 0; i < 4; i++) {
            int row = lrow + i * 32;
            const unsigned* src = A + (size_t)(bm + row) * lda + k0 + lc8 * 4;
            unsigned dst = sbase + (row * SKA + lc8 * 4) * 4;
            asm volatile("cp.async.cg.shared.global [%0], [%1], 16;" :: "r"(dst), "l"(src));
        }
        unsigned sbase_b = sbase + TILE_WORDS * 4;
        #pragma unroll
        for (int i = 0; i < 4; i++) {
            int row = lrow + i * 32;
            int gn = bn + row;
            int ok = (gn < N) ? 16 : 0;
            const unsigned* src = B + (size_t)(gn < N ? gn : 0) * ldb + k0 + lc8 * 4;
            unsigned dst = sbase_b + (row * SKA + lc8 * 4) * 4;
            asm volatile("cp.async.cg.shared.global [%0], [%1], 16, %2;" :: "r"(dst), "l"(src), "r"(ok));
        }
    };

    float acc[4][4][4];
    #pragma unroll
    for (int i = 0; i < 4; i++)
        #pragma unroll
        for (int j = 0; j < 4; j++)
            #pragma unroll
            for (int q = 0; q < 4; q++) acc[i][j][q] = 0.f;

    // prologue: stages 0..STG-2
    #pragma unroll
    for (int s = 0; s < STG - 1; s++) {
        if (s < ktiles) load_stage(s, s);
        asm volatile("cp.async.commit_group;");
    }

    for (int kt = 0; kt < ktiles; kt++) {
        if (kt >= ktiles - 1) asm volatile("cp.async.wait_group 0;");
        else                  asm volatile("cp.async.wait_group 1;");
        __syncthreads();

        const unsigned* As_ = sm + (kt % STG) * STAGE_WORDS + (warpM + g) * SKA + t;
        const unsigned* Bs_ = sm + (kt % STG) * STAGE_WORDS + TILE_WORDS + (warpN + g) * SKA + t;

        #pragma unroll
        for (int ks = 0; ks < 4; ks++) {
            unsigned a[4][4], b[4][2];
            #pragma unroll
            for (int mt = 0; mt < 4; mt++) {
                a[mt][0] = As_[mt * 16 * SKA + ks * 8];
                a[mt][1] = As_[mt * 16 * SKA + 8 * SKA + ks * 8];
                a[mt][2] = As_[mt * 16 * SKA + ks * 8 + 4];
                a[mt][3] = As_[mt * 16 * SKA + 8 * SKA + ks * 8 + 4];
            }
            #pragma unroll
            for (int nt = 0; nt < 4; nt++) {
                b[nt][0] = Bs_[nt * 8 * SKA + ks * 8];
                b[nt][1] = Bs_[nt * 8 * SKA + ks * 8 + 4];
            }
            #pragma unroll
            for (int nt = 0; nt < 4; nt++)
                #pragma unroll
                for (int mt = 0; mt < 4; mt++)
                    mma_tf32(acc[mt][nt], a[mt][0], a[mt][1], a[mt][2], a[mt][3],
                             b[nt][0], b[nt][1]);
        }

        if (kt + STG - 1 < ktiles) load_stage((kt + STG - 1) % STG, kt + STG - 1);
        asm volatile("cp.async.commit_group;");
    }

    // epilogue
    #pragma unroll
    for (int mt = 0; mt < 4; mt++) {
        int gm = bm + warpM + mt * 16 + g;
        #pragma unroll
        for (int nt = 0; nt < 4; nt++) {
            int gn = bn + warpN + nt * 8 + t * 2;
            if (gn < N) {
                float2 v0 = make_float2(acc[mt][nt][0], acc[mt][nt][1]);
                float2 v1 = make_float2(acc[mt][nt][2], acc[mt][nt][3]);
                if (EPI == 1) {
                    float b0 = bias[gn], b1 = bias[gn + 1];
                    v0.x = softplusf(v0.x + b0);
                    v0.y = softplusf(v0.y + b1);
                    v1.x = softplusf(v1.x + b0);
                    v1.y = softplusf(v1.y + b1);
                }
                *(float2*)(C + (size_t)gm * ldc + gn)       = v0;
                *(float2*)(C + (size_t)(gm + 8) * ldc + gn) = v1;
            }
        }
    }
}

// ---------------------------------------------------------------------------
// x_proj split-K reduce: sum 8 partials -> fp32 + tf32
// ---------------------------------------------------------------------------
__global__ __launch_bounds__(256)
void xp_reduce_kernel()
{
    int i = blockIdx.x * 256 + threadIdx.x;
    if (i >= ROWS * XDBL_COLS) return;
    float s = 0.f;
    #pragma unroll
    for (int p = 0; p < XP_SPLITS; p++)
        s += g_xpart[(size_t)p * ROWS * XDBL_COLS + i];
    g_xdbl[i]  = s;
    g_xdblt[i] = f2tf(s);
}

// ---------------------------------------------------------------------------
// Depthwise causal conv + bias + SiLU -> fp32 (scan) and tf32 (x_proj A)
// ---------------------------------------------------------------------------
__global__ __launch_bounds__(256)
void conv_silu_kernel(const float* __restrict__ xz,
                      const float* __restrict__ cw,
                      const float* __restrict__ cb,
                      float* __restrict__ xc,
                      unsigned* __restrict__ xct)
{
    int idx = blockIdx.x * blockDim.x + threadIdx.x;
    if (idx >= ROWS * D_INNER) return;
    int d = idx & (D_INNER - 1);
    int r = idx >> 11;
    int l = r & (SEQLEN - 1);
    int b = r >> 10;

    float acc = cb[d];
    #pragma unroll
    for (int k = 0; k < D_CONV; k++) {
        int ls = l + k - (D_CONV - 1);
        if (ls >= 0)
            acc = fmaf(xz[((size_t)(b * SEQLEN + ls)) * (2 * D_INNER) + d],
                       cw[d * D_CONV + k], acc);
    }
    float sig = 1.0f / (1.0f + __expf(-acc));
    float v = acc * sig;
    xc[idx]  = v;
    xct[idx] = f2tf(v);
}

// ---------------------------------------------------------------------------
// Selective scan. 16 lanes per (b,d) channel. Output tf32 (feeds out_proj).
// ---------------------------------------------------------------------------
__global__ __launch_bounds__(128)
void scan_kernel(const float* __restrict__ xdbl,
                 const float* __restrict__ dt,
                 const float* __restrict__ xc,
                 const float* __restrict__ xz,
                 const float* __restrict__ A_log,
                 const float* __restrict__ Dw,
                 unsigned* __restrict__ y)
{
    int t = blockIdx.x * blockDim.x + threadIdx.x;
    int n  = t & (D_STATE - 1);
    int ch = t >> 4;
    int b  = ch >> 11;
    int d  = ch & (D_INNER - 1);

    float A  = -__expf(A_log[d * D_STATE + n]);
    float Dd = Dw[d];

    const float* xdbl_b = xdbl + (size_t)b * SEQLEN * XDBL_COLS;
    const float* dt_b   = dt   + (size_t)b * SEQLEN * D_INNER + d;
    const float* xc_b   = xc   + (size_t)b * SEQLEN * D_INNER + d;
    const float* z_b    = xz   + (size_t)b * SEQLEN * (2 * D_INNER) + D_INNER + d;
    unsigned*    y_b    = y    + (size_t)b * SEQLEN * D_INNER + d;

    float h = 0.f;
    for (int l = 0; l < SEQLEN; l++) {
        float dtv = dt_b[(size_t)l * D_INNER];
        float xcv = xc_b[(size_t)l * D_INNER];
        float Bv  = xdbl_b[l * XDBL_COLS + DT_RANK + n];
        float Cv  = xdbl_b[l * XDBL_COLS + DT_RANK + D_STATE + n];

        float dA = __expf(dtv * A);
        h = fmaf(dA, h, dtv * xcv * Bv);

        float p = h * Cv;
        p += __shfl_xor_sync(0xffffffffu, p, 8);
        p += __shfl_xor_sync(0xffffffffu, p, 4);
        p += __shfl_xor_sync(0xffffffffu, p, 2);
        p += __shfl_xor_sync(0xffffffffu, p, 1);

        if (n == 0) {
            float zv  = z_b[(size_t)l * (2 * D_INNER)];
            float sil = zv / (1.0f + __expf(-zv));
            y_b[(size_t)l * D_INNER] = f2tf((p + Dd * xcv) * sil);
        }
    }
}

// ---------------------------------------------------------------------------
// Launch
// ---------------------------------------------------------------------------
extern "C" void kernel_launch(void* const* d_in, const int* in_sizes, int n_in,
                              void* d_out, int out_size)
{
    const float* hidden   = (const float*)d_in[0];
    const float* norm_w   = (const float*)d_in[1];
    const float* in_proj  = (const float*)d_in[2];
    const float* conv_w   = (const float*)d_in[3];
    const float* conv_b   = (const float*)d_in[4];
    const float* x_proj   = (const float*)d_in[5];
    const float* dt_proj  = (const float*)d_in[6];
    const float* dt_b     = (const float*)d_in[7];
    const float* A_log    = (const float*)d_in[8];
    const float* Dw       = (const float*)d_in[9];
    const float* out_proj = (const float*)d_in[10];

    float* out = (float*)d_out;

    unsigned *ht, *xct, *xdblt, *yt, *wi, *wo, *wx, *wd;
    float *xz, *xc, *xpart, *xdbl, *dt;
    cudaGetSymbolAddress((void**)&ht,    g_ht);
    cudaGetSymbolAddress((void**)&xz,    g_xz);
    cudaGetSymbolAddress((void**)&xc,    g_xc);
    cudaGetSymbolAddress((void**)&xct,   g_xct);
    cudaGetSymbolAddress((void**)&xpart, g_xpart);
    cudaGetSymbolAddress((void**)&xdbl,  g_xdbl);
    cudaGetSymbolAddress((void**)&xdblt, g_xdblt);
    cudaGetSymbolAddress((void**)&dt,    g_dt);
    cudaGetSymbolAddress((void**)&yt,    g_yt);
    cudaGetSymbolAddress((void**)&wi,    g_wi);
    cudaGetSymbolAddress((void**)&wo,    g_wo);
    cudaGetSymbolAddress((void**)&wx,    g_wx);
    cudaGetSymbolAddress((void**)&wd,    g_wd);

    cudaFuncSetAttribute(gemm_tc<0>, cudaFuncAttributeMaxDynamicSharedMemorySize, GEMM_SMEM);
    cudaFuncSetAttribute(gemm_tc<1>, cudaFuncAttributeMaxDynamicSharedMemorySize, GEMM_SMEM);

    // 0. weight conversion (tf32)
    cvt_weights_kernel<<<(NW_TOTAL + 255) / 256, 256>>>(in_proj, out_proj, x_proj, dt_proj);

    // 1. RMSNorm -> tf32
    rmsnorm_kernel<<<ROWS, 256>>>(hidden, norm_w, ht);

    // 2. in_proj: (2048 x 1024) @ (4096 x 1024)^T -> xz (2048 x 4096)
    gemm_tc<0><<<dim3(2 * D_INNER / 128, ROWS / 128, 1), 256, GEMM_SMEM>>>(
        ht, D_MODEL, wi, D_MODEL, xz, 2 * D_INNER,
        2 * D_INNER, D_MODEL, 0, nullptr);

    // 3. conv + silu -> xc (fp32) + xct (tf32)
    conv_silu_kernel<<<(ROWS * D_INNER) / 256, 256>>>(xz, conv_w, conv_b, xc, xct);

    // 4. x_proj split-K: (2048 x 2048) @ (96 x 2048)^T -> 8 partials (2048 x 96)
    gemm_tc<0><<<dim3(1, ROWS / 128, XP_SPLITS), 256, GEMM_SMEM>>>(
        xct, D_INNER, wx, D_INNER, xpart, XDBL_COLS,
        XDBL_COLS, XP_KSPL, (long long)ROWS * XDBL_COLS, nullptr);

    // 4b. reduce partials -> xdbl (fp32) + xdblt (tf32)
    xp_reduce_kernel<<<(ROWS * XDBL_COLS + 255) / 256, 256>>>();

    // 5. dt_proj + softplus: (2048 x 96[:64]) @ (2048 x 64)^T -> dt (2048 x 2048)
    gemm_tc<1><<<dim3(D_INNER / 128, ROWS / 128, 1), 256, GEMM_SMEM>>>(
        xdblt, XDBL_COLS, wd, DT_RANK, dt, D_INNER,
        D_INNER, DT_RANK, 0, dt_b);

    // 6. selective scan + gate -> yt (tf32)
    scan_kernel<<<(BATCH * D_INNER * D_STATE) / 128, 128>>>(
        xdbl, dt, xc, xz, A_log, Dw, yt);

    // 7. out_proj: (2048 x 2048) @ (1024 x 2048)^T -> out (2048 x 1024)
    gemm_tc<0><<<dim3(D_MODEL / 128, ROWS / 128, 1), 256, GEMM_SMEM>>>(
        yt, D_INNER, wo, D_INNER, out, D_MODEL,
        D_MODEL, D_INNER, 0, nullptr);

    // 8. residual
    size_t half = (size_t)out_size / 2;
    cudaMemcpyAsync(out + half, hidden, half * sizeof(float),
                    cudaMemcpyDeviceToDevice);
}